// round 6
// baseline (speedup 1.0000x reference)
#include <cuda_runtime.h>
#include <math.h>

// Problem constants
#define R_    2048
#define C_    1024
#define NCH   8

#define RPB   8                  // rows per KA block
#define NKA   (R_ / RPB)         // 256 KA blocks
#define NKB   128                // KB blocks
#define CPB   (C_ / NKB)         // 8 columns per KB block

// Scratch (no allocations allowed -> device globals)
__device__ float g_lq[R_ * NCH];     // log prod_ba(1-P) per (row, ch)  64KB
__device__ float g_pA[64 * NKA];     // [colP64][kaBlock256] partial sum_r P*s
__device__ float g_pB[64 * NKA];     // [colP64][kaBlock256] partial sum_r P
__device__ float g_pSel[NKA];        // per-KA-block row-sel partial
__device__ float g_ncolB[NCH * NKB]; // [ch][kbBlock] colch partial sums
__device__ unsigned int g_count = 0; // KB completion ticket (self-resetting)

// ---------------------------------------------------------------------------
// KA: 256 blocks x 256 threads, 8 rows each.
//  Stage A: 8 warps x 1 row -> softmax over 64, write P + g_lq, stage sel.
//  Stage B: stream the 8x1024 D tile (float4) -> per-row sums only.
//  Stage C: pA/pB/sel per-block partials.
// ---------------------------------------------------------------------------
__global__ __launch_bounds__(256) void ka_rows(const float* __restrict__ W,
                                               const float* __restrict__ D,
                                               const float* __restrict__ G,
                                               float* __restrict__ outP)
{
    __shared__ float sP[RPB][64];
    __shared__ float sds[RPB][8];
    __shared__ float sSel[RPB];
    __shared__ float sS[RPB];

    const int t    = threadIdx.x;
    const int wid  = t >> 5;          // 0..7
    const int lane = t & 31;
    const int r0   = blockIdx.x * RPB;

    const float2* W2 = reinterpret_cast<const float2*>(W);
    const float2* G2 = reinterpret_cast<const float2*>(G);

    // ---- Stage A: one row per warp ----
    {
        const int rl = wid;
        const int r  = r0 + rl;

        float2 w  = W2[r * 32 + lane];
        float2 gv = G2[r * 32 + lane];
        float e0 = w.x + gv.x;
        float e1 = w.y + gv.y;

        float m = fmaxf(e0, e1);
        #pragma unroll
        for (int o = 16; o > 0; o >>= 1)
            m = fmaxf(m, __shfl_xor_sync(0xFFFFFFFFu, m, o));

        float x0 = expf(e0 - m);
        float x1 = expf(e1 - m);
        float s  = x0 + x1;
        #pragma unroll
        for (int o = 16; o > 0; o >>= 1)
            s += __shfl_xor_sync(0xFFFFFFFFu, s, o);

        const float inv = 1.0f / s;      // == max(P): exp(0)=1 at the argmax
        const float p0  = x0 * inv;
        const float p1  = x1 * inv;

        reinterpret_cast<float2*>(outP)[r * 32 + lane] = make_float2(p0, p1);
        sP[rl][2 * lane]     = p0;
        sP[rl][2 * lane + 1] = p1;

        float lq = log1pf(-p0) + log1pf(-p1);
        lq += __shfl_xor_sync(0xFFFFFFFFu, lq, 1);
        lq += __shfl_xor_sync(0xFFFFFFFFu, lq, 2);
        if ((lane & 3) == 0) g_lq[r * NCH + (lane >> 2)] = lq;
        if (lane == 0) sSel[rl] = (inv > 0.99f) ? 1.0f : 0.0f;
    }
    __syncthreads();

    // ---- Stage B: stream D tile, row sums only ----
    float dsv[RPB];
    const float4* D4 = reinterpret_cast<const float4*>(D);
    #pragma unroll
    for (int rl = 0; rl < RPB; rl++) {
        float4 d = D4[(size_t)(r0 + rl) * 256 + t];
        dsv[rl] = (d.x + d.y) + (d.z + d.w);
    }
    #pragma unroll
    for (int rl = 0; rl < RPB; rl++) {
        float v = dsv[rl];
        #pragma unroll
        for (int o = 16; o > 0; o >>= 1)
            v += __shfl_xor_sync(0xFFFFFFFFu, v, o);
        if (lane == 0) sds[rl][wid] = v;
    }
    __syncthreads();

    if (t < RPB) {
        float v = 0.f;
        #pragma unroll
        for (int w2 = 0; w2 < 8; w2++) v += sds[t][w2];
        sS[t] = v;
    }
    __syncthreads();

    // ---- Stage C: partials ----
    if (t < 64) {
        float a = 0.f, b = 0.f;
        #pragma unroll
        for (int rl = 0; rl < RPB; rl++) {
            float p = sP[rl][t];
            b += p;
            a  = fmaf(p, sS[rl], a);
        }
        g_pA[t * NKA + blockIdx.x] = a;
        g_pB[t * NKA + blockIdx.x] = b;
    }
    if (t == 0) {
        float v = 0.f;
        #pragma unroll
        for (int rl = 0; rl < RPB; rl++) v += sSel[rl];
        g_pSel[blockIdx.x] = v;
    }
}

// ---------------------------------------------------------------------------
// KB: 128 blocks x 512 threads; block owns 8 columns. Computes the COMPLETE
// L[c][ch] = sum_r D[r,c]*lq[r,ch] in-block (2 row-passes of 1024, lq staged
// in smem), colch = 1-exp(L), per-block ncol partials. Last block finalizes.
// Output layout (float32, concatenated tuple):
//   P[131072] | tot[8] | max_nnz[8] | num_col[8] | num_row[8] |
//   nnz_ch_ba[64] | col_density[8] | num_row_sel[1]
// ---------------------------------------------------------------------------
__global__ __launch_bounds__(512) void kb_cols(const float* __restrict__ D,
                                               float* __restrict__ out)
{
    __shared__ float4 slq4[1024 * 2];     // lq tile: 1024 rows x 8 ch  (32KB)
    __shared__ float  swacc[16 * 64];     // per-warp (col,ch) partials  (4KB)
    __shared__ float  sLcc[64];
    __shared__ float  sncol2[16];

    const int t    = threadIdx.x;
    const int lane = t & 31;
    const int wid  = t >> 5;              // 0..15
    const int col  = t & 7;               // 0..7
    const int rgrp = t >> 3;              // 0..63
    const int b    = blockIdx.x;
    const int c    = b * CPB + col;

    float4 acc0 = make_float4(0.f, 0.f, 0.f, 0.f);
    float4 acc1 = make_float4(0.f, 0.f, 0.f, 0.f);

    const float4* lq4 = reinterpret_cast<const float4*>(g_lq);

    #pragma unroll
    for (int pass = 0; pass < 2; pass++) {
        // stage 1024 rows of lq into smem (coalesced float4)
        #pragma unroll
        for (int k = 0; k < 4; k++)
            slq4[t + 512 * k] = lq4[pass * 2048 + t + 512 * k];
        __syncthreads();

        #pragma unroll
        for (int j = 0; j < 16; j++) {
            const int rl = rgrp * 16 + j;                 // 0..1023
            const float d = D[(size_t)(pass * 1024 + rl) * C_ + c];
            float4 l0 = slq4[rl * 2];
            float4 l1 = slq4[rl * 2 + 1];
            acc0.x = fmaf(d, l0.x, acc0.x);
            acc0.y = fmaf(d, l0.y, acc0.y);
            acc0.z = fmaf(d, l0.z, acc0.z);
            acc0.w = fmaf(d, l0.w, acc0.w);
            acc1.x = fmaf(d, l1.x, acc1.x);
            acc1.y = fmaf(d, l1.y, acc1.y);
            acc1.z = fmaf(d, l1.z, acc1.z);
            acc1.w = fmaf(d, l1.w, acc1.w);
        }
        __syncthreads();
    }

    // ---- reduce over the 4 rgrps inside each warp (lanes differ in bits 3,4) ----
    float a[8] = {acc0.x, acc0.y, acc0.z, acc0.w, acc1.x, acc1.y, acc1.z, acc1.w};
    #pragma unroll
    for (int ch = 0; ch < 8; ch++) {
        a[ch] += __shfl_xor_sync(0xFFFFFFFFu, a[ch], 8);
        a[ch] += __shfl_xor_sync(0xFFFFFFFFu, a[ch], 16);
    }
    if (lane < 8) {
        #pragma unroll
        for (int ch = 0; ch < 8; ch++)
            swacc[wid * 64 + lane * 8 + ch] = a[ch];   // lane == col here
    }
    __syncthreads();

    // ---- combine 16 warps -> L[col][ch]; colch = 1-exp ----
    if (t < 64) {
        float L = 0.f;
        #pragma unroll
        for (int w2 = 0; w2 < 16; w2++) L += swacc[w2 * 64 + t];
        float colch = 1.0f - expf(L);
        sLcc[t] = colch;                       // t = colq*8 + ch
        // reduce over cols within each 32-thread warp (cols differ in bits 3,4)
        colch += __shfl_xor_sync(0xFFFFFFFFu, colch, 8);
        colch += __shfl_xor_sync(0xFFFFFFFFu, colch, 16);
        if (lane < 8) sncol2[(t >> 5) * 8 + lane] = colch;   // two half-partials
    }
    __syncthreads();
    if (t < 8)
        g_ncolB[t * NKB + b] = sncol2[t] + sncol2[8 + t];

    // ---- completion ticket: last block finalizes ----
    __shared__ int isLast;
    __threadfence();
    if (t == 0) {
        unsigned int old = atomicAdd(&g_count, 1u);
        isLast = (old == NKB - 1) ? 1 : 0;
        if (isLast) g_count = 0;               // reset for next graph replay
    }
    __syncthreads();
    if (!isLast) return;
    __threadfence();                            // acquire other blocks' writes

    __shared__ float snn[64], sps[64], sncol[NCH], ssel[1];

    // 16 warps x 4 outputs: reduce pA & pB over 256 KA blocks (coalesced)
    #pragma unroll
    for (int k = 0; k < 4; k++) {
        const int o = wid * 4 + k;
        float va = 0.f, vb = 0.f;
        #pragma unroll
        for (int j = 0; j < 8; j++) {
            va += g_pA[o * NKA + lane + 32 * j];
            vb += g_pB[o * NKA + lane + 32 * j];
        }
        #pragma unroll
        for (int off = 16; off > 0; off >>= 1) {
            va += __shfl_xor_sync(0xFFFFFFFFu, va, off);
            vb += __shfl_xor_sync(0xFFFFFFFFu, vb, off);
        }
        if (lane == 0) { snn[o] = va; sps[o] = vb; }
    }
    if (wid == 0) {                            // sel over 256 KA blocks
        float v = 0.f;
        #pragma unroll
        for (int j = 0; j < 8; j++) v += g_pSel[lane + 32 * j];
        #pragma unroll
        for (int off = 16; off > 0; off >>= 1)
            v += __shfl_xor_sync(0xFFFFFFFFu, v, off);
        if (lane == 0) ssel[0] = v;
    }
    if (wid == 1) {                            // ncol over 128 KB blocks
        #pragma unroll
        for (int ch = 0; ch < NCH; ch++) {
            float v = g_ncolB[ch * NKB + lane]      + g_ncolB[ch * NKB + lane + 32]
                    + g_ncolB[ch * NKB + lane + 64] + g_ncolB[ch * NKB + lane + 96];
            #pragma unroll
            for (int off = 16; off > 0; off >>= 1)
                v += __shfl_xor_sync(0xFFFFFFFFu, v, off);
            if (lane == 0) sncol[ch] = v;
        }
    }
    __syncthreads();

    if (t < 64) out[131104 + t] = snn[t];       // nnz_ch_ba

    if (t < NCH) {
        float m = -1e30f, ns = 0.f, rs = 0.f;
        #pragma unroll
        for (int ba = 0; ba < 8; ba++) {
            float nv = snn[t * 8 + ba];
            m  = fmaxf(m, nv);
            ns += nv;
            rs += sps[t * 8 + ba];
        }
        float ncl = sncol[t];
        out[131072 + t] = m + ncl + rs;         // tot_ch
        out[131080 + t] = m;                    // max_nnz_ch
        out[131088 + t] = ncl;                  // num_col_ch
        out[131096 + t] = rs;                   // num_row_ch
        out[131168 + t] = ns / rs / ncl;        // col_density_ch
    }
    if (t == 0) out[131176] = ssel[0];          // num_row_sel
}

// ---------------------------------------------------------------------------
extern "C" void kernel_launch(void* const* d_in, const int* in_sizes, int n_in,
                              void* d_out, int out_size)
{
    const float* W = (const float*)d_in[0];   // [2048, 64]
    const float* D = (const float*)d_in[1];   // [2048, 1024]
    const float* G = (const float*)d_in[2];   // [2048, 64]
    // d_in[3] = i, unused by the math
    float* out = (float*)d_out;

    ka_rows<<<NKA, 256>>>(W, D, G, out);
    kb_cols<<<NKB, 512>>>(D, out);
}

// round 7
// speedup vs baseline: 1.1358x; 1.1358x over previous
#include <cuda_runtime.h>
#include <math.h>

// Problem constants
#define R_    2048
#define C_    1024
#define NCH   8

#define RPB   16                 // rows per block (phase 1)
#define NBLK  128                // grid size; must be <= 148 for the grid barrier

// Scratch (no allocations allowed -> device globals)
__device__ float g_Lpart[NBLK * NCH * C_];   // per-block partial log-sums (4MB)
__device__ float g_pA[64 * NBLK];            // [col64][blk128] partial sum_r P*s
__device__ float g_pB[64 * NBLK];            // [col64][blk128] partial sum_r P
__device__ float g_pSel[NBLK];               // per-block row-sel partial
__device__ float g_nnz[64];                  // reduced nnz_ch_ba
__device__ float g_psum[64];                 // reduced sum_r P per (ch,ba)
__device__ float g_ncolPart[NBLK];           // per-block colch sums (phase 2)
__device__ float g_selv;                     // reduced row-sel count
__device__ unsigned int g_sync1 = 0;         // grid barrier (self-resetting)
__device__ unsigned int g_count = 0;         // finalize ticket (self-resetting)

// ---------------------------------------------------------------------------
// Single persistent kernel, 128 blocks x 512 threads.
// Phase 1: per block, 16 rows: softmax -> P; stream the 16x1024 D tile once
//          (float2/thread) computing 8-ch log-product FMAs + row sums;
//          write Lpart + pA/pB/sel partials.
// Grid barrier (all 128 blocks are co-resident on 148 SMs).
// Phase 2: block b reduces 64 (ch,c) outputs over the 128 L2-hot partials;
//          colch = 1-exp; idle warps reduce pA/pB/sel; ticket block finalizes.
// Output layout (float32, concatenated tuple):
//   P[131072] | tot[8] | max_nnz[8] | num_col[8] | num_row[8] |
//   nnz_ch_ba[64] | col_density[8] | num_row_sel[1]
// ---------------------------------------------------------------------------
__global__ __launch_bounds__(512) void k_all(const float* __restrict__ W,
                                             const float* __restrict__ D,
                                             const float* __restrict__ G,
                                             float* __restrict__ out)
{
    __shared__ float sP[RPB][64];
    __shared__ float slq[RPB][NCH];
    __shared__ float sds[RPB][16];
    __shared__ float sSel[RPB];
    __shared__ float sS[RPB];

    const int t    = threadIdx.x;
    const int wid  = t >> 5;          // 0..15
    const int lane = t & 31;
    const int b    = blockIdx.x;
    const int r0   = b * RPB;

    const float2* W2 = reinterpret_cast<const float2*>(W);
    const float2* G2 = reinterpret_cast<const float2*>(G);

    // ================= Phase 1 =================
    // ---- softmax: one row per warp ----
    {
        const int rl = wid;
        const int r  = r0 + rl;

        float2 w  = W2[r * 32 + lane];
        float2 gv = G2[r * 32 + lane];
        float e0 = w.x + gv.x;
        float e1 = w.y + gv.y;

        float m = fmaxf(e0, e1);
        #pragma unroll
        for (int o = 16; o > 0; o >>= 1)
            m = fmaxf(m, __shfl_xor_sync(0xFFFFFFFFu, m, o));

        float x0 = expf(e0 - m);
        float x1 = expf(e1 - m);
        float s  = x0 + x1;
        #pragma unroll
        for (int o = 16; o > 0; o >>= 1)
            s += __shfl_xor_sync(0xFFFFFFFFu, s, o);

        const float inv = 1.0f / s;      // == max(P): exp(0)=1 at the argmax
        const float p0  = x0 * inv;
        const float p1  = x1 * inv;

        reinterpret_cast<float2*>(out)[r * 32 + lane] = make_float2(p0, p1);
        sP[rl][2 * lane]     = p0;
        sP[rl][2 * lane + 1] = p1;

        float lq = log1pf(-p0) + log1pf(-p1);
        lq += __shfl_xor_sync(0xFFFFFFFFu, lq, 1);
        lq += __shfl_xor_sync(0xFFFFFFFFu, lq, 2);
        if ((lane & 3) == 0) slq[rl][lane >> 2] = lq;
        if (lane == 0) sSel[rl] = (inv > 0.99f) ? 1.0f : 0.0f;
    }
    __syncthreads();

    // ---- stream D tile once; 2 cols/thread; FMAs + row sums ----
    float accx[NCH], accy[NCH];
    #pragma unroll
    for (int ch = 0; ch < NCH; ch++) { accx[ch] = 0.f; accy[ch] = 0.f; }
    float dsv[RPB];

    const float2* D2 = reinterpret_cast<const float2*>(D);
    #pragma unroll
    for (int rl = 0; rl < RPB; rl++) {
        float2 d = D2[(size_t)(r0 + rl) * 512 + t];
        dsv[rl] = d.x + d.y;
        #pragma unroll
        for (int ch = 0; ch < NCH; ch++) {
            float l = slq[rl][ch];
            accx[ch] = fmaf(d.x, l, accx[ch]);
            accy[ch] = fmaf(d.y, l, accy[ch]);
        }
    }
    #pragma unroll
    for (int rl = 0; rl < RPB; rl++) {
        float v = dsv[rl];
        #pragma unroll
        for (int o = 16; o > 0; o >>= 1)
            v += __shfl_xor_sync(0xFFFFFFFFu, v, o);
        if (lane == 0) sds[rl][wid] = v;
    }

    // ---- write Lpart ----
    #pragma unroll
    for (int ch = 0; ch < NCH; ch++) {
        *reinterpret_cast<float2*>(
            &g_Lpart[((size_t)b * NCH + ch) * C_ + 2 * t]) =
            make_float2(accx[ch], accy[ch]);
    }
    __syncthreads();

    if (t < RPB) {
        float v = 0.f;
        #pragma unroll
        for (int w2 = 0; w2 < 16; w2++) v += sds[t][w2];
        sS[t] = v;
    }
    __syncthreads();

    if (t < 64) {
        float a = 0.f, bb = 0.f;
        #pragma unroll
        for (int rl = 0; rl < RPB; rl++) {
            float p = sP[rl][t];
            bb += p;
            a   = fmaf(p, sS[rl], a);
        }
        g_pA[t * NBLK + b] = a;
        g_pB[t * NBLK + b] = bb;
    }
    if (t == 0) {
        float v = 0.f;
        #pragma unroll
        for (int rl = 0; rl < RPB; rl++) v += sSel[rl];
        g_pSel[b] = v;
    }

    // ================= Grid barrier =================
    __syncthreads();
    if (t == 0) {
        __threadfence();
        atomicAdd(&g_sync1, 1u);
        while (atomicAdd(&g_sync1, 0u) < NBLK) __nanosleep(32);
        __threadfence();
    }
    __syncthreads();

    // ================= Phase 2 =================
    // block b owns 64 outputs o in [b*64, b*64+64); 8 k-groups x 64 outputs;
    // each thread sums 16 of the 128 partials (L2-hot, fully unrolled).
    {
        const int ol = t & 63;
        const int kg = t >> 6;            // 0..7
        const int o  = b * 64 + ol;
        const float* base = g_Lpart + (size_t)(kg * 16) * (NCH * C_) + o;
        float a0 = base[ 0 * (NCH * C_)], a1 = base[ 1 * (NCH * C_)];
        float a2 = base[ 2 * (NCH * C_)], a3 = base[ 3 * (NCH * C_)];
        float a4 = base[ 4 * (NCH * C_)], a5 = base[ 5 * (NCH * C_)];
        float a6 = base[ 6 * (NCH * C_)], a7 = base[ 7 * (NCH * C_)];
        float a8 = base[ 8 * (NCH * C_)], a9 = base[ 9 * (NCH * C_)];
        float aA = base[10 * (NCH * C_)], aB = base[11 * (NCH * C_)];
        float aC = base[12 * (NCH * C_)], aD = base[13 * (NCH * C_)];
        float aE = base[14 * (NCH * C_)], aF = base[15 * (NCH * C_)];
        __shared__ float red[8][64];
        red[kg][ol] = (((a0 + a1) + (a2 + a3)) + ((a4 + a5) + (a6 + a7)))
                    + (((a8 + a9) + (aA + aB)) + ((aC + aD) + (aE + aF)));
        __syncthreads();

        __shared__ float cs[2];
        if (t < 64) {
            float L = 0.f;
            #pragma unroll
            for (int k = 0; k < 8; k++) L += red[k][t];
            float colch = 1.0f - expf(L);
            #pragma unroll
            for (int off = 16; off > 0; off >>= 1)
                colch += __shfl_xor_sync(0xFFFFFFFFu, colch, off);
            if (lane == 0) cs[t >> 5] = colch;
        }

        // idle warps: reduce pA / pB / sel (coalesced rows of 128)
        if (wid == 8 && b < 64) {
            float a = g_pA[b * NBLK + lane]      + g_pA[b * NBLK + lane + 32]
                    + g_pA[b * NBLK + lane + 64] + g_pA[b * NBLK + lane + 96];
            #pragma unroll
            for (int off = 16; off > 0; off >>= 1)
                a += __shfl_xor_sync(0xFFFFFFFFu, a, off);
            if (lane == 0) g_nnz[b] = a;
        } else if (wid == 9 && b < 64) {
            float a = g_pB[b * NBLK + lane]      + g_pB[b * NBLK + lane + 32]
                    + g_pB[b * NBLK + lane + 64] + g_pB[b * NBLK + lane + 96];
            #pragma unroll
            for (int off = 16; off > 0; off >>= 1)
                a += __shfl_xor_sync(0xFFFFFFFFu, a, off);
            if (lane == 0) g_psum[b] = a;
        } else if (wid == 10 && b == 64) {
            float a = g_pSel[lane]      + g_pSel[lane + 32]
                    + g_pSel[lane + 64] + g_pSel[lane + 96];
            #pragma unroll
            for (int off = 16; off > 0; off >>= 1)
                a += __shfl_xor_sync(0xFFFFFFFFu, a, off);
            if (lane == 0) g_selv = a;
        }
        __syncthreads();
        if (t == 0) g_ncolPart[b] = cs[0] + cs[1];
    }

    // ---- completion ticket: last block finalizes ----
    __shared__ int isLast;
    __threadfence();
    if (t == 0) {
        unsigned int old = atomicAdd(&g_count, 1u);
        isLast = (old == NBLK - 1) ? 1 : 0;
        if (isLast) { g_count = 0; g_sync1 = 0; }   // reset for next replay
    }
    __syncthreads();
    if (!isLast) return;
    __threadfence();                                 // acquire other blocks

    if (t < 64) out[131104 + t] = g_nnz[t];          // nnz_ch_ba

    if (t < NCH) {
        float m = -1e30f, ns = 0.f, rs = 0.f;
        #pragma unroll
        for (int ba = 0; ba < 8; ba++) {
            float nv = g_nnz[t * 8 + ba];
            m  = fmaxf(m, nv);
            ns += nv;
            rs += g_psum[t * 8 + ba];
        }
        float ncl = 0.f;
        #pragma unroll
        for (int k = 0; k < 16; k++) ncl += g_ncolPart[t * 16 + k];
        out[131072 + t] = m + ncl + rs;              // tot_ch
        out[131080 + t] = m;                         // max_nnz_ch
        out[131088 + t] = ncl;                       // num_col_ch
        out[131096 + t] = rs;                        // num_row_ch
        out[131168 + t] = ns / rs / ncl;             // col_density_ch
    }
    if (t == 0) out[131176] = g_selv;                // num_row_sel
}

// ---------------------------------------------------------------------------
extern "C" void kernel_launch(void* const* d_in, const int* in_sizes, int n_in,
                              void* d_out, int out_size)
{
    const float* W = (const float*)d_in[0];   // [2048, 64]
    const float* D = (const float*)d_in[1];   // [2048, 1024]
    const float* G = (const float*)d_in[2];   // [2048, 64]
    // d_in[3] = i, unused by the math
    float* out = (float*)d_out;

    k_all<<<NBLK, 512>>>(W, D, G, out);
}